// round 15
// baseline (speedup 1.0000x reference)
#include <cuda_runtime.h>
#include <cuda_fp16.h>
#include <math.h>
#include <stdint.h>
#include <mma.h>

using namespace nvcuda;

// Problem constants (GCNII_30794915512599)
#define NN   100000      // nodes
#define NE   1600000     // edges
#define FIN  512
#define HID  128
#define NC   64
#define NL   8

#define GEMM_BLOCKS ((NN + 127) / 128)          // 782
#define SC_BLOCKS   ((NE + 255) / 256)          // 6250
#define PERSIST_BLOCKS 304                       // 2/SM x 152 SMs

// tf32 input-GEMM smem: As[2][128][36] + Bs[2][32][132]; C overlays
#define ASTRIDE 36
#define BSTRIDE 132
#define CSTRIDE 132
#define IN_AS_STAGE (128 * ASTRIDE)
#define IN_BS_STAGE (32 * BSTRIDE)
#define IN_SMEM_FLOATS (2 * IN_AS_STAGE + 2 * IN_BS_STAGE)   // 17664
#define INGEMM_SMEM (IN_SMEM_FLOATS * 4)         // 70656 B

// fp16 layer-GEMM smem: Ah[128][136] + Bh[128][136] halfs
// C fp32 overlays Ah only: [64][132] = 33792 B <= 34816 B
#define AH_STRIDE 136
#define LGEMM_SMEM (2 * 128 * AH_STRIDE * 2)     // 69632 B

// ---------------- scratch (static __device__ — no allocations) ----------------
__device__ int    d_cnt[NN];     // zero-init at load; re-zeroed by k_out each launch
__device__ int    d_fill[NN];
__device__ int    d_rowptr[NN + 1];
__device__ float  d_dinv[NN];
__device__ int    d_src[NE];
__device__ int    d_dst[NE];
__device__ int2   d_epack[NE];   // packed (src, weight-as-int)
__device__ __half d_h16 [(size_t)NN * HID];  // h  (fp16 only)
__device__ __half d_h016[(size_t)NN * HID];  // h0 (fp16 only)
__device__ __half d_s16 [(size_t)NN * HID];  // s  (fp16 only)
__device__ __half d_w16 [(size_t)NL * HID * HID];  // fp16 conv weights

// ---------------- cp.async helpers ----------------
__device__ __forceinline__ void cp_async16(uint32_t saddr, const void* gptr) {
    asm volatile("cp.async.ca.shared.global [%0], [%1], 16;"
                 :: "r"(saddr), "l"(gptr));
}
__device__ __forceinline__ void cp_commit() {
    asm volatile("cp.async.commit_group;");
}
__device__ __forceinline__ void cp_wait0() {
    asm volatile("cp.async.wait_group 0;");
}
__device__ __forceinline__ uint32_t smem_u32(const void* p) {
    return (uint32_t)__cvta_generic_to_shared(p);
}

// pack 8 floats -> 8 halfs (16B)
__device__ __forceinline__ uint4 pack_half8(const float* v) {
    __half2 q0 = __floats2half2_rn(v[0], v[1]);
    __half2 q1 = __floats2half2_rn(v[2], v[3]);
    __half2 q2 = __floats2half2_rn(v[4], v[5]);
    __half2 q3 = __floats2half2_rn(v[6], v[7]);
    uint4 u;
    u.x = *(uint32_t*)&q0; u.y = *(uint32_t*)&q1;
    u.z = *(uint32_t*)&q2; u.w = *(uint32_t*)&q3;
    return u;
}
// unpack 8 halfs (uint4) -> 8 floats
__device__ __forceinline__ void unpack_half8(uint4 u, float* v) {
    float2 a = __half22float2(*(__half2*)&u.x);
    float2 b = __half22float2(*(__half2*)&u.y);
    float2 c = __half22float2(*(__half2*)&u.z);
    float2 d = __half22float2(*(__half2*)&u.w);
    v[0] = a.x; v[1] = a.y; v[2] = b.x; v[3] = b.y;
    v[4] = c.x; v[5] = c.y; v[6] = d.x; v[7] = d.y;
}

// ---------------- edge prep (with inline per-warp dtype detection) ----------
// edge_index is logically int64 but JAX without x64 emits int32. int32 pairs
// read as uint64 are >= 2^32 whenever the high word is nonzero; true int64
// indices are < 100000.
__global__ __launch_bounds__(256) void k_prep_edges(const void* eiv) {
    const int lane = threadIdx.x & 31;
    const unsigned long long* q = (const unsigned long long*)eiv;
    bool big = false;
#pragma unroll
    for (int k = 0; k < 2; k++) {
        int idx = (lane + k * 32) * 31;      // samples in [0, 1953]
        big |= (q[idx] > 0xFFFFFFFFull);
    }
    bool is64 = !__any_sync(0xffffffff, big);

    int e = blockIdx.x * blockDim.x + threadIdx.x;
    if (e >= NE) return;
    int s, d;
    if (is64) {
        const long long* ei = (const long long*)eiv;
        s = (int)ei[e];
        d = (int)ei[(size_t)NE + e];
    } else {
        const int* ei = (const int*)eiv;
        s = ei[e];
        d = ei[NE + e];
    }
    s = min(max(s, 0), NN - 1);
    d = min(max(d, 0), NN - 1);
    d_src[e] = s;
    d_dst[e] = d;
    atomicAdd(&d_cnt[d], 1);
}

// single-block exclusive scan over d_cnt -> d_rowptr, fused with dinv compute
__global__ __launch_bounds__(1024) void k_scan_dinv() {
    __shared__ int buf[1024];
    const int t = threadIdx.x;
    const int CH = (NN + 1023) / 1024;   // 98
    const int start = t * CH;
    int s = 0;
    for (int j = 0; j < CH; j++) {
        int idx = start + j;
        if (idx < NN) s += d_cnt[idx];
    }
    buf[t] = s;
    __syncthreads();
    for (int off = 1; off < 1024; off <<= 1) {
        int v = (t >= off) ? buf[t - off] : 0;
        __syncthreads();
        buf[t] += v;
        __syncthreads();
    }
    int run = (t == 0) ? 0 : buf[t - 1];
    for (int j = 0; j < CH; j++) {
        int idx = start + j;
        if (idx < NN) {
            int c = d_cnt[idx];
            d_rowptr[idx] = run;
            d_dinv[idx] = rsqrtf((float)(c + 1));   // +1 self loop
            run += c;
        }
    }
    if (t == 1023) d_rowptr[NN] = buf[1023];
}

// ---------------- conv weight fp32 -> fp16 mirror (once per launch) --------
__global__ __launch_bounds__(256) void k_wconv(const float* __restrict__ CW) {
    int idx = blockIdx.x * 256 + threadIdx.x;    // 32768 threads x 4 floats
    float4 v = *(const float4*)(CW + (size_t)idx * 4);
    __half2 q0 = __floats2half2_rn(v.x, v.y);
    __half2 q1 = __floats2half2_rn(v.z, v.w);
    uint2 u;
    u.x = *(uint32_t*)&q0; u.y = *(uint32_t*)&q1;
    *(uint2*)(d_w16 + (size_t)idx * 4) = u;
}

// ---------------- fused: tf32 input GEMM (blocks [0,782)) + scatter (rest) --
// gemm: h = x @ w_in + b_in ; writes h16 and h016 (fp16 only)
__global__ __launch_bounds__(256, 2) void k_gemm_in_scatter(
        const float* __restrict__ X, const float* __restrict__ W,
        const float* __restrict__ B) {
    if (blockIdx.x >= GEMM_BLOCKS) {
        int e = (blockIdx.x - GEMM_BLOCKS) * 256 + threadIdx.x;
        if (e < NE) {
            int s = d_src[e], d = d_dst[e];
            int pos = d_rowptr[d] + atomicAdd(&d_fill[d], 1);
            float w = d_dinv[s] * d_dinv[d];
            d_epack[pos] = make_int2(s, __float_as_int(w));
        }
        return;
    }
    extern __shared__ float sm[];
    float* As[2] = { sm, sm + IN_AS_STAGE };
    float* Bs[2] = { sm + 2 * IN_AS_STAGE, sm + 2 * IN_AS_STAGE + IN_BS_STAGE };
    const int tid = threadIdx.x;
    const int blockRow = blockIdx.x * 128;
    const int warp = tid >> 5;
    const int wr = warp >> 2;            // 0..1
    const int wc = warp & 3;             // 0..3

    const int ar = tid >> 1, ac = tid & 1;
    const int brr = tid >> 3, bcc = tid & 7;

    wmma::fragment<wmma::accumulator, 16, 16, 8, float> cf[4][2];
#pragma unroll
    for (int r = 0; r < 4; r++)
#pragma unroll
        for (int c = 0; c < 2; c++)
            wmma::fill_fragment(cf[r][c], 0.f);

    const int asrc0 = min(blockRow + ar, NN - 1);

    auto issue_stage = [&](int buf, int k0) {
#pragma unroll
        for (int j = 0; j < 4; j++) {
            int c = ac + j * 2;
            cp_async16(smem_u32(&As[buf][ar * ASTRIDE + c * 4]),
                       X + (size_t)asrc0 * FIN + k0 + c * 4);
        }
#pragma unroll
        for (int j = 0; j < 4; j++) {
            int c = bcc + j * 8;
            cp_async16(smem_u32(&Bs[buf][brr * BSTRIDE + c * 4]),
                       W + (size_t)(k0 + brr) * HID + c * 4);
        }
        cp_commit();
    };

    issue_stage(0, 0);
    int p = 0;
    for (int s = 0; s < FIN / 32; s++) {
        cp_wait0();
        __syncthreads();
        if (s + 1 < FIN / 32) issue_stage(p ^ 1, (s + 1) * 32);
#pragma unroll
        for (int kk = 0; kk < 32; kk += 8) {
            wmma::fragment<wmma::matrix_a, 16, 16, 8, wmma::precision::tf32,
                           wmma::row_major> af[4];
            wmma::fragment<wmma::matrix_b, 16, 16, 8, wmma::precision::tf32,
                           wmma::row_major> bf[2];
#pragma unroll
            for (int r = 0; r < 4; r++) {
                wmma::load_matrix_sync(af[r],
                    &As[p][(wr * 64 + r * 16) * ASTRIDE + kk], ASTRIDE);
#pragma unroll
                for (int t = 0; t < af[r].num_elements; t++)
                    af[r].x[t] = wmma::__float_to_tf32(af[r].x[t]);
            }
#pragma unroll
            for (int c = 0; c < 2; c++) {
                wmma::load_matrix_sync(bf[c],
                    &Bs[p][kk * BSTRIDE + wc * 32 + c * 16], BSTRIDE);
#pragma unroll
                for (int t = 0; t < bf[c].num_elements; t++)
                    bf[c].x[t] = wmma::__float_to_tf32(bf[c].x[t]);
            }
#pragma unroll
            for (int r = 0; r < 4; r++)
#pragma unroll
                for (int c = 0; c < 2; c++)
                    wmma::mma_sync(cf[r][c], af[r], bf[c], cf[r][c]);
        }
        p ^= 1;
    }
    __syncthreads();

    float* Cs = sm;                      // [128][CSTRIDE]
#pragma unroll
    for (int r = 0; r < 4; r++)
#pragma unroll
        for (int c = 0; c < 2; c++)
            wmma::store_matrix_sync(
                &Cs[(wr * 64 + r * 16) * CSTRIDE + wc * 32 + c * 16],
                cf[r][c], CSTRIDE, wmma::mem_row_major);
    __syncthreads();

    const int tx = tid & 15, ty = tid >> 4;
    float bi[8];
    *(float4*)&bi[0] = *(const float4*)(B + tx * 8);
    *(float4*)&bi[4] = *(const float4*)(B + tx * 8 + 4);
#pragma unroll
    for (int i = 0; i < 8; i++) {
        int rl = ty * 8 + i;
        int row = blockRow + rl;
        if (row >= NN) continue;
        float ov[8];
        *(float4*)&ov[0] = *(float4*)&Cs[rl * CSTRIDE + tx * 8];
        *(float4*)&ov[4] = *(float4*)&Cs[rl * CSTRIDE + tx * 8 + 4];
#pragma unroll
        for (int j = 0; j < 8; j++) ov[j] += bi[j];
        uint4 hv = pack_half8(ov);
        *(uint4*)(d_h16  + (size_t)row * HID + tx * 8) = hv;
        *(uint4*)(d_h016 + (size_t)row * HID + tx * 8) = hv;
    }
}

// ---------------- aggregation: s = 0.9*(norm-adj @ h) + 0.1*h0 ----------------
// TWO nodes per warp: lanes 0-15 -> node 2w, lanes 16-31 -> node 2w+1.
// Each lane owns a 16B chunk (8 halfs) of its node's row. 8-way edge unroll.
__global__ __launch_bounds__(256, 3) void k_agg() {
    const int warpId = blockIdx.x * 8 + (threadIdx.x >> 5);
    const int lane = threadIdx.x & 31;
    const int sub = lane & 15;                // chunk id within row
    const int i = warpId * 2 + (lane >> 4);   // node (grid sized exactly)
    const uint4* h16 = (const uint4*)d_h16;   // 16 x 16B chunks per row

    float di = d_dinv[i];
    float wself = di * di;
    float a0[8], a1[8];
    {
        float sv[8];
        unpack_half8(__ldg(&h16[(size_t)i * 16 + sub]), sv);
#pragma unroll
        for (int j = 0; j < 8; j++) { a0[j] = wself * sv[j]; a1[j] = 0.f; }
    }

    const int beg = d_rowptr[i];
    const int end = d_rowptr[i + 1];
    int e = beg;
    while (__any_sync(0xffffffffu, e < end)) {
        int   src[8];
        float ww[8];
        uint4 vv[8];
#pragma unroll
        for (int k = 0; k < 8; k++) {
            int idx = e + k;
            bool valid = idx < end;
            idx = valid ? idx : 0;
            int2 p = __ldg(&d_epack[idx]);
            src[k] = p.x;
            ww[k] = valid ? __int_as_float(p.y) : 0.f;
        }
#pragma unroll
        for (int k = 0; k < 8; k++)
            vv[k] = __ldg(&h16[(size_t)src[k] * 16 + sub]);
#pragma unroll
        for (int k = 0; k < 8; k++) {
            float v[8];
            unpack_half8(vv[k], v);
            float* acc = (k & 1) ? a1 : a0;
#pragma unroll
            for (int j = 0; j < 8; j++) acc[j] += ww[k] * v[j];
        }
        e += 8;
    }

    float h0v[8];
    unpack_half8(__ldg((const uint4*)d_h016 + (size_t)i * 16 + sub), h0v);
    float o[8];
#pragma unroll
    for (int j = 0; j < 8; j++)
        o[j] = 0.9f * (a0[j] + a1[j]) + 0.1f * h0v[j];
    ((uint4*)d_s16)[(size_t)i * 16 + sub] = pack_half8(o);
}

// ---------------- persistent layer GEMM (fp16 HMMA) + mix + ELU ------------
// h = elu((1-beta)*s + beta*(s @ W)); W tile resident, blocks loop over tiles.
// Split epilogue: C fp32 staged 64 rows at a time, overlaying Ah only.
__global__ __launch_bounds__(256, 2) void k_gemm_layer(int layer, float beta) {
    extern __shared__ float sm[];
    __half* Ah = (__half*)sm;                 // [128][AH_STRIDE] (34816 B)
    __half* Bh = Ah + 128 * AH_STRIDE;        // [128][AH_STRIDE] (resident)
    float*  Cs = sm;                          // overlay on Ah: [64][CSTRIDE]
    const int tid = threadIdx.x;
    const int warp = tid >> 5;
    const int wr = warp >> 2;
    const int wc = warp & 3;
    const int tx = tid & 15, ty = tid >> 4;
    const float omb = 1.f - beta;
    const __half* Wl = d_w16 + (size_t)layer * HID * HID;

    // load resident W tile once
#pragma unroll
    for (int j = 0; j < 8; j++) {
        int idx = tid + j * 256;
        int r = idx >> 4, c8 = idx & 15;
        *(uint4*)&Bh[r * AH_STRIDE + c8 * 8] =
            *(const uint4*)(Wl + (size_t)r * HID + c8 * 8);
    }

    for (int tile = blockIdx.x; tile < GEMM_BLOCKS; tile += gridDim.x) {
        const int blockRow = tile * 128;
        // load A (s16) tile
#pragma unroll
        for (int j = 0; j < 8; j++) {
            int idx = tid + j * 256;
            int r = idx >> 4, c8 = idx & 15;
            int grow = blockRow + r;
            uint4 raw = make_uint4(0, 0, 0, 0);
            if (grow < NN)
                raw = *(const uint4*)(d_s16 + (size_t)grow * HID + c8 * 8);
            *(uint4*)&Ah[r * AH_STRIDE + c8 * 8] = raw;
        }
        __syncthreads();

        wmma::fragment<wmma::accumulator, 16, 16, 16, float> cf[4][2];
#pragma unroll
        for (int r = 0; r < 4; r++)
#pragma unroll
            for (int c = 0; c < 2; c++)
                wmma::fill_fragment(cf[r][c], 0.f);

#pragma unroll
        for (int kk = 0; kk < 8; kk++) {
            wmma::fragment<wmma::matrix_a, 16, 16, 16, __half, wmma::row_major> af[4];
            wmma::fragment<wmma::matrix_b, 16, 16, 16, __half, wmma::row_major> bf[2];
#pragma unroll
            for (int r = 0; r < 4; r++)
                wmma::load_matrix_sync(af[r],
                    &Ah[(wr * 64 + r * 16) * AH_STRIDE + kk * 16], AH_STRIDE);
#pragma unroll
            for (int c = 0; c < 2; c++)
                wmma::load_matrix_sync(bf[c],
                    &Bh[(kk * 16) * AH_STRIDE + wc * 32 + c * 16], AH_STRIDE);
#pragma unroll
            for (int r = 0; r < 4; r++)
#pragma unroll
                for (int c = 0; c < 2; c++)
                    wmma::mma_sync(cf[r][c], af[r], bf[c], cf[r][c]);
        }
        __syncthreads();   // Ah reads complete before Cs overlays it

        // split epilogue: half h covers global rows blockRow + h*64 ..
#pragma unroll
        for (int h = 0; h < 2; h++) {
            if (wr == h) {
#pragma unroll
                for (int r = 0; r < 4; r++)
#pragma unroll
                    for (int c = 0; c < 2; c++)
                        wmma::store_matrix_sync(
                            &Cs[(r * 16) * CSTRIDE + wc * 32 + c * 16],
                            cf[r][c], CSTRIDE, wmma::mem_row_major);
            }
            __syncthreads();
#pragma unroll
            for (int i = 0; i < 4; i++) {
                int rl = ty * 4 + i;             // 0..63
                int row = blockRow + h * 64 + rl;
                if (row >= NN) continue;
                float sv[8];
                uint4 sraw = *(const uint4*)(d_s16 + (size_t)row * HID + tx * 8);
                unpack_half8(sraw, sv);
                float av[8];
                *(float4*)&av[0] = *(float4*)&Cs[rl * CSTRIDE + tx * 8];
                *(float4*)&av[4] = *(float4*)&Cs[rl * CSTRIDE + tx * 8 + 4];
                float ov[8];
#pragma unroll
                for (int j = 0; j < 8; j++) {
                    float v = omb * sv[j] + beta * av[j];
                    ov[j] = (v > 0.f) ? v : expm1f(v);
                }
                *(uint4*)(d_h16 + (size_t)row * HID + tx * 8) = pack_half8(ov);
            }
            __syncthreads();
        }
    }
}

// ---------------- output GEMM + log_softmax (+ counter re-zero) -------------
__global__ __launch_bounds__(256) void k_out(const float* __restrict__ Wo,
                                             const float* __restrict__ Bo,
                                             float* __restrict__ out) {
    int gid = blockIdx.x * blockDim.x + threadIdx.x;
    if (gid < NN) { d_cnt[gid] = 0; d_fill[gid] = 0; }

    __shared__ float ws[128][64];   // 32 KB
    __shared__ float hs[32][128];   // 16 KB
    const int tid = threadIdx.x;
    const int base = blockIdx.x * 32;
#pragma unroll
    for (int j = 0; j < 8; j++) {
        int idx = tid + j * 256;
        int r = idx >> 4, c4 = idx & 15;
        *(float4*)&ws[r][c4 * 4] = *(const float4*)(Wo + (size_t)r * NC + c4 * 4);
    }
#pragma unroll
    for (int j = 0; j < 2; j++) {
        int idx = tid + j * 256;
        int r = idx >> 4, c8 = idx & 15;
        uint4 raw = *(const uint4*)(d_h16 + (size_t)(base + r) * HID + c8 * 8);
        float v[8];
        unpack_half8(raw, v);
        *(float4*)&hs[r][c8 * 8]     = *(float4*)&v[0];
        *(float4*)&hs[r][c8 * 8 + 4] = *(float4*)&v[4];
    }
    __syncthreads();
    const int w = tid >> 5, lane = tid & 31;
    float b0 = Bo[lane], b1 = Bo[lane + 32];
    float acc[4][2];
#pragma unroll
    for (int r = 0; r < 4; r++) { acc[r][0] = 0.f; acc[r][1] = 0.f; }
    for (int k = 0; k < HID; k++) {
        float wv0 = ws[k][lane];
        float wv1 = ws[k][lane + 32];
#pragma unroll
        for (int r = 0; r < 4; r++) {
            float hv = hs[w * 4 + r][k];
            acc[r][0] += hv * wv0;
            acc[r][1] += hv * wv1;
        }
    }
#pragma unroll
    for (int r = 0; r < 4; r++) {
        int row = base + w * 4 + r;
        float v0 = acc[r][0] + b0;
        float v1 = acc[r][1] + b1;
        float m = fmaxf(v0, v1);
#pragma unroll
        for (int off = 16; off; off >>= 1)
            m = fmaxf(m, __shfl_xor_sync(0xffffffff, m, off));
        float ssum = expf(v0 - m) + expf(v1 - m);
#pragma unroll
        for (int off = 16; off; off >>= 1)
            ssum += __shfl_xor_sync(0xffffffff, ssum, off);
        float lse = m + logf(ssum);
        out[(size_t)row * NC + lane]      = v0 - lse;
        out[(size_t)row * NC + lane + 32] = v1 - lse;
    }
}

// ---------------- launch ----------------
extern "C" void kernel_launch(void* const* d_in, const int* in_sizes, int n_in,
                              void* d_out, int out_size) {
    const float* x      = (const float*)d_in[0];
    const void*  ei     = d_in[1];
    const float* w_in   = (const float*)d_in[2];
    const float* b_in   = (const float*)d_in[3];
    const float* conv_w = (const float*)d_in[4];
    const float* w_out  = (const float*)d_in[5];
    const float* b_out  = (const float*)d_in[6];
    float*       out    = (float*)d_out;

    cudaFuncSetAttribute(k_gemm_in_scatter,
                         cudaFuncAttributeMaxDynamicSharedMemorySize, INGEMM_SMEM);
    cudaFuncSetAttribute(k_gemm_layer,
                         cudaFuncAttributeMaxDynamicSharedMemorySize, LGEMM_SMEM);

    k_prep_edges<<<SC_BLOCKS, 256>>>(ei);                               // 0
    k_scan_dinv<<<1, 1024>>>();                                         // 1
    k_wconv<<<(NL * HID * HID / 4 + 255) / 256, 256>>>(conv_w);         // 2
    k_gemm_in_scatter<<<GEMM_BLOCKS + SC_BLOCKS, 256, INGEMM_SMEM>>>(
        x, w_in, b_in);                                                 // 3 = profiled

    for (int l = 0; l < NL; l++) {                                      // 4..
        float beta = (float)log(0.5 / (double)(l + 1) + 1.0);
        k_agg<<<NN / 16, 256>>>();
        k_gemm_layer<<<PERSIST_BLOCKS, 256, LGEMM_SMEM>>>(l, beta);
    }

    k_out<<<NN / 32, 256>>>(w_out, b_out, out);
}

// round 16
// speedup vs baseline: 1.0974x; 1.0974x over previous
#include <cuda_runtime.h>
#include <cuda_fp16.h>
#include <math.h>
#include <stdint.h>
#include <mma.h>

using namespace nvcuda;

// Problem constants (GCNII_30794915512599)
#define NN   100000      // nodes
#define NE   1600000     // edges
#define FIN  512
#define HID  128
#define NC   64
#define NL   8

#define GEMM_BLOCKS ((NN + 127) / 128)          // 782
#define SC_BLOCKS   ((NE + 255) / 256)          // 6250

// fp16 input-GEMM smem: 2 stages of (A[128][40] + B[32][136]) halfs; C overlays
#define GIN_AST 40
#define GIN_BST 136
#define GIN_STAGE_HALFS (128 * GIN_AST + 32 * GIN_BST)   // 9472
#define CSTRIDE 132
#define INGEMM_SMEM (128 * CSTRIDE * 4)          // 67584 B (> 2 stages = 37888)

// fp16 layer-GEMM smem: Ah[128][136] + Bh[128][136] halfs; C fp32 overlays
#define AH_STRIDE 136
#define LGEMM_SMEM (2 * 128 * AH_STRIDE * 2)     // 69632 B

// ---------------- scratch (static __device__ — no allocations) ----------------
__device__ int    d_cnt[NN];     // zero-init at load; re-zeroed by k_out each launch
__device__ int    d_fill[NN];
__device__ int    d_rowptr[NN + 1];
__device__ float  d_dinv[NN];
__device__ int    d_src[NE];
__device__ int    d_dst[NE];
__device__ int2   d_epack[NE];   // packed (src, weight-as-int)
__device__ __half d_h16 [(size_t)NN * HID];  // h  (fp16 only)
__device__ __half d_h016[(size_t)NN * HID];  // h0 (fp16 only)
__device__ __half d_s16 [(size_t)NN * HID];  // s  (fp16 only)
__device__ __half d_w16 [(size_t)NL * HID * HID];  // fp16 conv weights

// pack 8 floats -> 8 halfs (16B)
__device__ __forceinline__ uint4 pack_half8(const float* v) {
    __half2 q0 = __floats2half2_rn(v[0], v[1]);
    __half2 q1 = __floats2half2_rn(v[2], v[3]);
    __half2 q2 = __floats2half2_rn(v[4], v[5]);
    __half2 q3 = __floats2half2_rn(v[6], v[7]);
    uint4 u;
    u.x = *(uint32_t*)&q0; u.y = *(uint32_t*)&q1;
    u.z = *(uint32_t*)&q2; u.w = *(uint32_t*)&q3;
    return u;
}
// unpack 8 halfs (uint4) -> 8 floats
__device__ __forceinline__ void unpack_half8(uint4 u, float* v) {
    float2 a = __half22float2(*(__half2*)&u.x);
    float2 b = __half22float2(*(__half2*)&u.y);
    float2 c = __half22float2(*(__half2*)&u.z);
    float2 d = __half22float2(*(__half2*)&u.w);
    v[0] = a.x; v[1] = a.y; v[2] = b.x; v[3] = b.y;
    v[4] = c.x; v[5] = c.y; v[6] = d.x; v[7] = d.y;
}

// ---------------- edge prep (with inline per-warp dtype detection) ----------
// edge_index is logically int64 but JAX without x64 emits int32. int32 pairs
// read as uint64 are >= 2^32 whenever the high word is nonzero; true int64
// indices are < 100000.
__global__ __launch_bounds__(256) void k_prep_edges(const void* eiv) {
    const int lane = threadIdx.x & 31;
    const unsigned long long* q = (const unsigned long long*)eiv;
    bool big = false;
#pragma unroll
    for (int k = 0; k < 2; k++) {
        int idx = (lane + k * 32) * 31;      // samples in [0, 1953]
        big |= (q[idx] > 0xFFFFFFFFull);
    }
    bool is64 = !__any_sync(0xffffffff, big);

    int e = blockIdx.x * blockDim.x + threadIdx.x;
    if (e >= NE) return;
    int s, d;
    if (is64) {
        const long long* ei = (const long long*)eiv;
        s = (int)ei[e];
        d = (int)ei[(size_t)NE + e];
    } else {
        const int* ei = (const int*)eiv;
        s = ei[e];
        d = ei[NE + e];
    }
    s = min(max(s, 0), NN - 1);
    d = min(max(d, 0), NN - 1);
    d_src[e] = s;
    d_dst[e] = d;
    atomicAdd(&d_cnt[d], 1);
}

// single-block exclusive scan over d_cnt -> d_rowptr, fused with dinv compute
__global__ __launch_bounds__(1024) void k_scan_dinv() {
    __shared__ int buf[1024];
    const int t = threadIdx.x;
    const int CH = (NN + 1023) / 1024;   // 98
    const int start = t * CH;
    int s = 0;
    for (int j = 0; j < CH; j++) {
        int idx = start + j;
        if (idx < NN) s += d_cnt[idx];
    }
    buf[t] = s;
    __syncthreads();
    for (int off = 1; off < 1024; off <<= 1) {
        int v = (t >= off) ? buf[t - off] : 0;
        __syncthreads();
        buf[t] += v;
        __syncthreads();
    }
    int run = (t == 0) ? 0 : buf[t - 1];
    for (int j = 0; j < CH; j++) {
        int idx = start + j;
        if (idx < NN) {
            int c = d_cnt[idx];
            d_rowptr[idx] = run;
            d_dinv[idx] = rsqrtf((float)(c + 1));   // +1 self loop
            run += c;
        }
    }
    if (t == 1023) d_rowptr[NN] = buf[1023];
}

// ---------------- conv weight fp32 -> fp16 mirror (once per launch) --------
__global__ __launch_bounds__(256) void k_wconv(const float* __restrict__ CW) {
    int idx = blockIdx.x * 256 + threadIdx.x;    // 32768 threads x 4 floats
    float4 v = *(const float4*)(CW + (size_t)idx * 4);
    __half2 q0 = __floats2half2_rn(v.x, v.y);
    __half2 q1 = __floats2half2_rn(v.z, v.w);
    uint2 u;
    u.x = *(uint32_t*)&q0; u.y = *(uint32_t*)&q1;
    *(uint2*)(d_w16 + (size_t)idx * 4) = u;
}

// ---------------- fused: fp16 input GEMM (blocks [0,782)) + scatter (rest) --
// gemm: h = x @ w_in + b_in ; writes h16 and h016.
// 128x128 tile, K=512 in 16 chunks of 32, fp16 HMMA, register-prefetch dbuf.
__global__ __launch_bounds__(256, 2) void k_gemm_in_scatter(
        const float* __restrict__ X, const float* __restrict__ W,
        const float* __restrict__ B) {
    if (blockIdx.x >= GEMM_BLOCKS) {
        int e = (blockIdx.x - GEMM_BLOCKS) * 256 + threadIdx.x;
        if (e < NE) {
            int s = d_src[e], d = d_dst[e];
            int pos = d_rowptr[d] + atomicAdd(&d_fill[d], 1);
            float w = d_dinv[s] * d_dinv[d];
            d_epack[pos] = make_int2(s, __float_as_int(w));
        }
        return;
    }
    extern __shared__ float sm[];
    const int tid = threadIdx.x;
    const int blockRow = blockIdx.x * 128;
    const int warp = tid >> 5;
    const int wr = warp >> 2;            // 0..1
    const int wc = warp & 3;             // 0..3

    // loader coords: A row + k-half, B k-row + col-chunk
    const int ar = tid >> 1, ac = tid & 1;       // A: row 0..127, 16-float seg
    const int br = tid >> 3, bc = tid & 7;       // B: k-row 0..31, 16-col seg
    const int asrc = min(blockRow + ar, NN - 1); // clamp (rows skipped in epi)

    auto stA = [&](int b) { return (__half*)sm + b * GIN_STAGE_HALFS; };
    auto stB = [&](int b) { return (__half*)sm + b * GIN_STAGE_HALFS + 128 * GIN_AST; };

    wmma::fragment<wmma::accumulator, 16, 16, 16, float> cf[4][2];
#pragma unroll
    for (int r = 0; r < 4; r++)
#pragma unroll
        for (int c = 0; c < 2; c++)
            wmma::fill_fragment(cf[r][c], 0.f);

    // ---- prologue: stage 0 ----
    {
        float a[16], b[16];
#pragma unroll
        for (int j = 0; j < 4; j++)
            *(float4*)&a[j * 4] = *(const float4*)(X + (size_t)asrc * FIN + ac * 16 + j * 4);
#pragma unroll
        for (int j = 0; j < 4; j++)
            *(float4*)&b[j * 4] = *(const float4*)(W + (size_t)br * HID + bc * 16 + j * 4);
        *(uint4*)&stA(0)[ar * GIN_AST + ac * 16]     = pack_half8(a);
        *(uint4*)&stA(0)[ar * GIN_AST + ac * 16 + 8] = pack_half8(a + 8);
        *(uint4*)&stB(0)[br * GIN_BST + bc * 16]     = pack_half8(b);
        *(uint4*)&stB(0)[br * GIN_BST + bc * 16 + 8] = pack_half8(b + 8);
    }
    __syncthreads();

    int p = 0;
    for (int s = 0; s < FIN / 32; s++) {
        const bool more = (s + 1 < FIN / 32);
        float a[16], b[16];
        if (more) {
            const int kn = (s + 1) * 32;
#pragma unroll
            for (int j = 0; j < 4; j++)
                *(float4*)&a[j * 4] =
                    *(const float4*)(X + (size_t)asrc * FIN + kn + ac * 16 + j * 4);
#pragma unroll
            for (int j = 0; j < 4; j++)
                *(float4*)&b[j * 4] =
                    *(const float4*)(W + (size_t)(kn + br) * HID + bc * 16 + j * 4);
        }
        // compute kk=0 (k 0..15 of this stage) while loads fly
        {
            wmma::fragment<wmma::matrix_a, 16, 16, 16, __half, wmma::row_major> af[4];
            wmma::fragment<wmma::matrix_b, 16, 16, 16, __half, wmma::row_major> bf[2];
#pragma unroll
            for (int r = 0; r < 4; r++)
                wmma::load_matrix_sync(af[r],
                    &stA(p)[(wr * 64 + r * 16) * GIN_AST], GIN_AST);
#pragma unroll
            for (int c = 0; c < 2; c++)
                wmma::load_matrix_sync(bf[c],
                    &stB(p)[wc * 32 + c * 16], GIN_BST);
#pragma unroll
            for (int r = 0; r < 4; r++)
#pragma unroll
                for (int c = 0; c < 2; c++)
                    wmma::mma_sync(cf[r][c], af[r], bf[c], cf[r][c]);
        }
        if (more) {
            *(uint4*)&stA(p ^ 1)[ar * GIN_AST + ac * 16]     = pack_half8(a);
            *(uint4*)&stA(p ^ 1)[ar * GIN_AST + ac * 16 + 8] = pack_half8(a + 8);
            *(uint4*)&stB(p ^ 1)[br * GIN_BST + bc * 16]     = pack_half8(b);
            *(uint4*)&stB(p ^ 1)[br * GIN_BST + bc * 16 + 8] = pack_half8(b + 8);
        }
        // compute kk=1 (k 16..31)
        {
            wmma::fragment<wmma::matrix_a, 16, 16, 16, __half, wmma::row_major> af[4];
            wmma::fragment<wmma::matrix_b, 16, 16, 16, __half, wmma::row_major> bf[2];
#pragma unroll
            for (int r = 0; r < 4; r++)
                wmma::load_matrix_sync(af[r],
                    &stA(p)[(wr * 64 + r * 16) * GIN_AST + 16], GIN_AST);
#pragma unroll
            for (int c = 0; c < 2; c++)
                wmma::load_matrix_sync(bf[c],
                    &stB(p)[16 * GIN_BST + wc * 32 + c * 16], GIN_BST);
#pragma unroll
            for (int r = 0; r < 4; r++)
#pragma unroll
                for (int c = 0; c < 2; c++)
                    wmma::mma_sync(cf[r][c], af[r], bf[c], cf[r][c]);
        }
        __syncthreads();
        p ^= 1;
    }

    // stage C into fp32 smem overlay
    float* Cs = sm;                      // [128][CSTRIDE]
#pragma unroll
    for (int r = 0; r < 4; r++)
#pragma unroll
        for (int c = 0; c < 2; c++)
            wmma::store_matrix_sync(
                &Cs[(wr * 64 + r * 16) * CSTRIDE + wc * 32 + c * 16],
                cf[r][c], CSTRIDE, wmma::mem_row_major);
    __syncthreads();

    // epilogue: + bias -> h16 and h016
    const int tx = tid & 15, ty = tid >> 4;
    float bi[8];
    *(float4*)&bi[0] = *(const float4*)(B + tx * 8);
    *(float4*)&bi[4] = *(const float4*)(B + tx * 8 + 4);
#pragma unroll
    for (int i = 0; i < 8; i++) {
        int rl = ty * 8 + i;
        int row = blockRow + rl;
        if (row >= NN) continue;
        float ov[8];
        *(float4*)&ov[0] = *(float4*)&Cs[rl * CSTRIDE + tx * 8];
        *(float4*)&ov[4] = *(float4*)&Cs[rl * CSTRIDE + tx * 8 + 4];
#pragma unroll
        for (int j = 0; j < 8; j++) ov[j] += bi[j];
        uint4 hv = pack_half8(ov);
        *(uint4*)(d_h16  + (size_t)row * HID + tx * 8) = hv;
        *(uint4*)(d_h016 + (size_t)row * HID + tx * 8) = hv;
    }
}

// ---------------- aggregation: s = 0.9*(norm-adj @ h) + 0.1*h0 ----------------
// TWO nodes per warp: lanes 0-15 -> node 2w, lanes 16-31 -> node 2w+1.
// Each lane owns a 16B chunk (8 halfs) of its node's row. 4-way edge unroll.
// (round-14 version — known good)
__global__ __launch_bounds__(256) void k_agg() {
    const int warpId = blockIdx.x * 8 + (threadIdx.x >> 5);
    const int lane = threadIdx.x & 31;
    const int sub = lane & 15;                // chunk id within row
    const int i = warpId * 2 + (lane >> 4);   // node (grid sized exactly)
    const uint4* h16 = (const uint4*)d_h16;   // 16 x 16B chunks per row

    float di = d_dinv[i];
    float wself = di * di;
    float a0[8], a1[8];
    {
        float sv[8];
        unpack_half8(__ldg(&h16[(size_t)i * 16 + sub]), sv);
#pragma unroll
        for (int j = 0; j < 8; j++) { a0[j] = wself * sv[j]; a1[j] = 0.f; }
    }

    const int beg = d_rowptr[i];
    const int end = d_rowptr[i + 1];
    int e = beg;
    while (__any_sync(0xffffffffu, e < end)) {
        int2 pp[4];
        float ww[4];
        uint4 vv[4];
#pragma unroll
        for (int k = 0; k < 4; k++) {
            int idx = e + k;
            bool valid = idx < end;
            idx = valid ? idx : 0;
            int2 p = __ldg(&d_epack[idx]);
            pp[k] = p;
            ww[k] = valid ? __int_as_float(p.y) : 0.f;
        }
#pragma unroll
        for (int k = 0; k < 4; k++)
            vv[k] = __ldg(&h16[(size_t)pp[k].x * 16 + sub]);
#pragma unroll
        for (int k = 0; k < 4; k++) {
            float v[8];
            unpack_half8(vv[k], v);
            float* acc = (k & 1) ? a1 : a0;
#pragma unroll
            for (int j = 0; j < 8; j++) acc[j] += ww[k] * v[j];
        }
        e += 4;
    }

    float h0v[8];
    unpack_half8(__ldg((const uint4*)d_h016 + (size_t)i * 16 + sub), h0v);
    float o[8];
#pragma unroll
    for (int j = 0; j < 8; j++)
        o[j] = 0.9f * (a0[j] + a1[j]) + 0.1f * h0v[j];
    ((uint4*)d_s16)[(size_t)i * 16 + sub] = pack_half8(o);
}

// ---------------- layer GEMM (fp16 HMMA) + identity-map mix + ELU ----------
// h = elu((1-beta)*s + beta*(s @ W)); round-14 version — known good
__global__ __launch_bounds__(256, 2) void k_gemm_layer(int layer, float beta) {
    extern __shared__ float sm[];
    __half* Ah = (__half*)sm;                 // [128][AH_STRIDE]
    __half* Bh = Ah + 128 * AH_STRIDE;        // [128][AH_STRIDE]
    const int tid = threadIdx.x;
    const int blockRow = blockIdx.x * 128;
    const int warp = tid >> 5;
    const int wr = warp >> 2;
    const int wc = warp & 3;
    const __half* Wl = d_w16 + (size_t)layer * HID * HID;

#pragma unroll
    for (int j = 0; j < 8; j++) {
        int idx = tid + j * 256;
        int r = idx >> 4, c8 = idx & 15;
        int grow = blockRow + r;
        uint4 raw = make_uint4(0, 0, 0, 0);
        if (grow < NN)
            raw = *(const uint4*)(d_s16 + (size_t)grow * HID + c8 * 8);
        *(uint4*)&Ah[r * AH_STRIDE + c8 * 8] = raw;
    }
#pragma unroll
    for (int j = 0; j < 8; j++) {
        int idx = tid + j * 256;
        int r = idx >> 4, c8 = idx & 15;
        *(uint4*)&Bh[r * AH_STRIDE + c8 * 8] =
            *(const uint4*)(Wl + (size_t)r * HID + c8 * 8);
    }
    __syncthreads();

    wmma::fragment<wmma::accumulator, 16, 16, 16, float> cf[4][2];
#pragma unroll
    for (int r = 0; r < 4; r++)
#pragma unroll
        for (int c = 0; c < 2; c++)
            wmma::fill_fragment(cf[r][c], 0.f);

#pragma unroll
    for (int kk = 0; kk < 8; kk++) {
        wmma::fragment<wmma::matrix_a, 16, 16, 16, __half, wmma::row_major> af[4];
        wmma::fragment<wmma::matrix_b, 16, 16, 16, __half, wmma::row_major> bf[2];
#pragma unroll
        for (int r = 0; r < 4; r++)
            wmma::load_matrix_sync(af[r],
                &Ah[(wr * 64 + r * 16) * AH_STRIDE + kk * 16], AH_STRIDE);
#pragma unroll
        for (int c = 0; c < 2; c++)
            wmma::load_matrix_sync(bf[c],
                &Bh[(kk * 16) * AH_STRIDE + wc * 32 + c * 16], AH_STRIDE);
#pragma unroll
        for (int r = 0; r < 4; r++)
#pragma unroll
            for (int c = 0; c < 2; c++)
                wmma::mma_sync(cf[r][c], af[r], bf[c], cf[r][c]);
    }
    __syncthreads();   // all fragment reads done before C overlays Ah/Bh

    float* Cs = sm;                      // [128][CSTRIDE] fp32 overlay
#pragma unroll
    for (int r = 0; r < 4; r++)
#pragma unroll
        for (int c = 0; c < 2; c++)
            wmma::store_matrix_sync(
                &Cs[(wr * 64 + r * 16) * CSTRIDE + wc * 32 + c * 16],
                cf[r][c], CSTRIDE, wmma::mem_row_major);
    __syncthreads();

    const int tx = tid & 15, ty = tid >> 4;
    const float omb = 1.f - beta;
#pragma unroll
    for (int i = 0; i < 8; i++) {
        int rl = ty * 8 + i;
        int row = blockRow + rl;
        if (row >= NN) continue;
        float sv[8];
        uint4 sraw = *(const uint4*)(d_s16 + (size_t)row * HID + tx * 8);
        unpack_half8(sraw, sv);
        float av[8];
        *(float4*)&av[0] = *(float4*)&Cs[rl * CSTRIDE + tx * 8];
        *(float4*)&av[4] = *(float4*)&Cs[rl * CSTRIDE + tx * 8 + 4];
        float ov[8];
#pragma unroll
        for (int j = 0; j < 8; j++) {
            float v = omb * sv[j] + beta * av[j];
            ov[j] = (v > 0.f) ? v : expm1f(v);
        }
        *(uint4*)(d_h16 + (size_t)row * HID + tx * 8) = pack_half8(ov);
    }
}

// ---------------- output GEMM + log_softmax (+ counter re-zero) -------------
__global__ __launch_bounds__(256) void k_out(const float* __restrict__ Wo,
                                             const float* __restrict__ Bo,
                                             float* __restrict__ out) {
    int gid = blockIdx.x * blockDim.x + threadIdx.x;
    if (gid < NN) { d_cnt[gid] = 0; d_fill[gid] = 0; }

    __shared__ float ws[128][64];   // 32 KB
    __shared__ float hs[32][128];   // 16 KB
    const int tid = threadIdx.x;
    const int base = blockIdx.x * 32;
#pragma unroll
    for (int j = 0; j < 8; j++) {
        int idx = tid + j * 256;
        int r = idx >> 4, c4 = idx & 15;
        *(float4*)&ws[r][c4 * 4] = *(const float4*)(Wo + (size_t)r * NC + c4 * 4);
    }
#pragma unroll
    for (int j = 0; j < 2; j++) {
        int idx = tid + j * 256;
        int r = idx >> 4, c8 = idx & 15;
        uint4 raw = *(const uint4*)(d_h16 + (size_t)(base + r) * HID + c8 * 8);
        float v[8];
        unpack_half8(raw, v);
        *(float4*)&hs[r][c8 * 8]     = *(float4*)&v[0];
        *(float4*)&hs[r][c8 * 8 + 4] = *(float4*)&v[4];
    }
    __syncthreads();
    const int w = tid >> 5, lane = tid & 31;
    float b0 = Bo[lane], b1 = Bo[lane + 32];
    float acc[4][2];
#pragma unroll
    for (int r = 0; r < 4; r++) { acc[r][0] = 0.f; acc[r][1] = 0.f; }
    for (int k = 0; k < HID; k++) {
        float wv0 = ws[k][lane];
        float wv1 = ws[k][lane + 32];
#pragma unroll
        for (int r = 0; r < 4; r++) {
            float hv = hs[w * 4 + r][k];
            acc[r][0] += hv * wv0;
            acc[r][1] += hv * wv1;
        }
    }
#pragma unroll
    for (int r = 0; r < 4; r++) {
        int row = base + w * 4 + r;
        float v0 = acc[r][0] + b0;
        float v1 = acc[r][1] + b1;
        float m = fmaxf(v0, v1);
#pragma unroll
        for (int off = 16; off; off >>= 1)
            m = fmaxf(m, __shfl_xor_sync(0xffffffff, m, off));
        float ssum = expf(v0 - m) + expf(v1 - m);
#pragma unroll
        for (int off = 16; off; off >>= 1)
            ssum += __shfl_xor_sync(0xffffffff, ssum, off);
        float lse = m + logf(ssum);
        out[(size_t)row * NC + lane]      = v0 - lse;
        out[(size_t)row * NC + lane + 32] = v1 - lse;
    }
}

// ---------------- launch ----------------
extern "C" void kernel_launch(void* const* d_in, const int* in_sizes, int n_in,
                              void* d_out, int out_size) {
    const float* x      = (const float*)d_in[0];
    const void*  ei     = d_in[1];
    const float* w_in   = (const float*)d_in[2];
    const float* b_in   = (const float*)d_in[3];
    const float* conv_w = (const float*)d_in[4];
    const float* w_out  = (const float*)d_in[5];
    const float* b_out  = (const float*)d_in[6];
    float*       out    = (float*)d_out;

    cudaFuncSetAttribute(k_gemm_in_scatter,
                         cudaFuncAttributeMaxDynamicSharedMemorySize, INGEMM_SMEM);
    cudaFuncSetAttribute(k_gemm_layer,
                         cudaFuncAttributeMaxDynamicSharedMemorySize, LGEMM_SMEM);

    k_prep_edges<<<SC_BLOCKS, 256>>>(ei);                               // 0
    k_scan_dinv<<<1, 1024>>>();                                         // 1
    k_wconv<<<(NL * HID * HID / 4 + 255) / 256, 256>>>(conv_w);         // 2
    k_gemm_in_scatter<<<GEMM_BLOCKS + SC_BLOCKS, 256, INGEMM_SMEM>>>(
        x, w_in, b_in);                                                 // 3 = profiled

    for (int l = 0; l < NL; l++) {                                      // 4..
        float beta = (float)log(0.5 / (double)(l + 1) + 1.0);
        k_agg<<<NN / 16, 256>>>();
        k_gemm_layer<<<GEMM_BLOCKS, 256, LGEMM_SMEM>>>(l, beta);
    }

    k_out<<<NN / 32, 256>>>(w_out, b_out, out);
}